// round 4
// baseline (speedup 1.0000x reference)
#include <cuda_runtime.h>
#include <cstdint>

// ---------------------------------------------------------------------------
// StressNNEval: fused SVD-invariants + 5-layer MLP (erf GELU) + stress epilogue
//
// Layout constants
// ---------------------------------------------------------------------------
#define MTILE   128          // rows per CTA
#define NH      256          // hidden width
#define LDA     264          // smem activation row stride (floats), conflict-free
#define LDW     260          // smem weight-chunk row stride (floats), conflict-free
#define KCHUNK  32           // K streamed per weight chunk
#define WCH_F   (KCHUNK*LDW) // floats per weight chunk buffer = 8320

#define SA_F    (MTILE*LDA)          // 33792
#define WBUF_F  (2*WCH_F)            // 16640
#define SR_F    (MTILE*9)            // 1152
#define SF_F    (MTILE*9)            // 1152
#define SW5_F   (NH*9)               // 2304
#define SMEM_F  (SA_F + WBUF_F + SR_F + SF_F + SW5_F)   // 55040 floats = 220160 B

__device__ __align__(16) float g_base1[256];

// ---------------------------------------------------------------------------
// small helpers
// ---------------------------------------------------------------------------
__device__ __forceinline__ uint32_t f2tf(float x) {
    uint32_t r;
    asm("cvt.rna.tf32.f32 %0, %1;" : "=r"(r) : "f"(x));
    return r;
}

__device__ __forceinline__ void mma8(float c[4], const uint32_t a[4], const uint32_t b[2]) {
    asm volatile(
        "mma.sync.aligned.m16n8k8.row.col.f32.tf32.tf32.f32 "
        "{%0,%1,%2,%3},{%4,%5,%6,%7},{%8,%9},{%0,%1,%2,%3};\n"
        : "+f"(c[0]), "+f"(c[1]), "+f"(c[2]), "+f"(c[3])
        : "r"(a[0]), "r"(a[1]), "r"(a[2]), "r"(a[3]), "r"(b[0]), "r"(b[1]));
}

__device__ __forceinline__ void cp16(float* s, const float* g) {
    uint32_t sa = (uint32_t)__cvta_generic_to_shared(s);
    asm volatile("cp.async.cg.shared.global [%0], [%1], 16;\n" :: "r"(sa), "l"(g));
}
__device__ __forceinline__ void cp_commit() { asm volatile("cp.async.commit_group;\n"); }
__device__ __forceinline__ void cp_wait0()  { asm volatile("cp.async.wait_group 0;\n"); }
__device__ __forceinline__ void cp_wait1()  { asm volatile("cp.async.wait_group 1;\n"); }

__device__ __forceinline__ float gelu_f(float x) {
    // exact (erf) GELU matching jax.nn.gelu(approximate=False)
    return 0.5f * x * (1.0f + erff(x * 0.70710678118654752f));
}

// ---------------------------------------------------------------------------
// one 32-wide K chunk of the 128x256 GEMM (tf32 mma.sync, 16 warps: 4x4 grid)
// K-permutation inside each k8: slot t -> k=2t, slot t+4 -> k=2t+1 (A and B
// use the same permutation -> result unchanged; enables LDS.64 A loads)
// ---------------------------------------------------------------------------
__device__ __forceinline__ void mma_chunk(const float* __restrict__ sA, int kA,
                                          const float* __restrict__ wch,
                                          float acc[2][8][4],
                                          int wm, int wn, int g, int t) {
#pragma unroll
    for (int k8 = 0; k8 < 4; ++k8) {
        const int kk = k8 * 8;
        uint32_t a[2][4];
#pragma unroll
        for (int mt = 0; mt < 2; ++mt) {
            const int row = wm * 32 + mt * 16 + g;
            const float2 lo = *(const float2*)&sA[row * LDA + kA + kk + 2 * t];
            const float2 hi = *(const float2*)&sA[(row + 8) * LDA + kA + kk + 2 * t];
            a[mt][0] = f2tf(lo.x); a[mt][2] = f2tf(lo.y);
            a[mt][1] = f2tf(hi.x); a[mt][3] = f2tf(hi.y);
        }
        uint32_t b[8][2];
#pragma unroll
        for (int nt = 0; nt < 8; ++nt) {
            const int col = wn * 64 + nt * 8 + g;
            b[nt][0] = f2tf(wch[(kk + 2 * t)     * LDW + col]);
            b[nt][1] = f2tf(wch[(kk + 2 * t + 1) * LDW + col]);
        }
#pragma unroll
        for (int mt = 0; mt < 2; ++mt)
#pragma unroll
            for (int nt = 0; nt < 8; ++nt)
                mma8(acc[mt][nt], a[mt], b[nt]);
    }
}

__device__ __forceinline__ void epilogue_gelu(float acc[2][8][4],
                                              const float* __restrict__ bias,
                                              float* __restrict__ sA,
                                              int wm, int wn, int g, int t) {
#pragma unroll
    for (int nt = 0; nt < 8; ++nt) {
        const int col = wn * 64 + nt * 8 + 2 * t;
        const float2 bb = *(const float2*)&bias[col];
#pragma unroll
        for (int mt = 0; mt < 2; ++mt) {
            const int row = wm * 32 + mt * 16 + g;
            float2 v0, v1;
            v0.x = gelu_f(acc[mt][nt][0] + bb.x);
            v0.y = gelu_f(acc[mt][nt][1] + bb.y);
            v1.x = gelu_f(acc[mt][nt][2] + bb.x);
            v1.y = gelu_f(acc[mt][nt][3] + bb.y);
            *(float2*)&sA[row * LDA + col]       = v0;
            *(float2*)&sA[(row + 8) * LDA + col] = v1;
        }
    }
}

// async-stage weight chunk c (32 rows x 256 cols) of W[256x256] into smem
__device__ __forceinline__ void stage_w(float* __restrict__ dst,
                                        const float* __restrict__ Wg,
                                        int chunk, int tid) {
    const float* src = Wg + chunk * KCHUNK * NH;
#pragma unroll
    for (int i = 0; i < 4; ++i) {
        const int e  = tid + i * 512;   // 0..2047 float4s
        const int kk = e >> 6;
        const int n4 = (e & 63) << 2;
        cp16(&dst[kk * LDW + n4], &src[kk * NH + n4]);
    }
}

// one streamed layer: acc = sA[128x256] @ W[256x256]; GELU(acc+bias) -> sA
__device__ __forceinline__ void run_layer(const float* __restrict__ Wg,
                                          const float* __restrict__ bias,
                                          float* __restrict__ sA,
                                          float* __restrict__ wbuf,
                                          int tid, int wm, int wn, int g, int t) {
    float acc[2][8][4];
#pragma unroll
    for (int mt = 0; mt < 2; ++mt)
#pragma unroll
        for (int nt = 0; nt < 8; ++nt)
#pragma unroll
            for (int i = 0; i < 4; ++i) acc[mt][nt][i] = 0.0f;

    stage_w(wbuf, Wg, 0, tid);
    cp_commit();
#pragma unroll 1
    for (int c = 0; c < 8; ++c) {
        if (c < 7) {
            stage_w(wbuf + ((c + 1) & 1) * WCH_F, Wg, c + 1, tid);
            cp_commit();
            cp_wait1();           // chunk c complete
        } else {
            cp_wait0();
        }
        __syncthreads();          // chunk c visible to all threads
        mma_chunk(sA, c * KCHUNK, wbuf + (c & 1) * WCH_F, acc, wm, wn, g, t);
        __syncthreads();          // reads of buf (c&1) done before chunk c+2 overwrites
    }
    epilogue_gelu(acc, bias, sA, wm, wn, g, t);
    __syncthreads();
}

// ---------------------------------------------------------------------------
// precompute base1 = b1 + emb[traj] @ W1[25:153, :]
// ---------------------------------------------------------------------------
__global__ void base1_kernel(const float* __restrict__ emb,
                             const int* __restrict__ traj,
                             const float* __restrict__ W1,
                             const float* __restrict__ b1) {
    const int n  = threadIdx.x;            // 0..255
    const int tr = traj ? traj[0] : 3;
    float s = b1[n];
    const float* e = emb + tr * 128;
#pragma unroll 8
    for (int d = 0; d < 128; ++d)
        s = fmaf(e[d], W1[(25 + d) * NH + n], s);
    g_base1[n] = s;
}

// ---------------------------------------------------------------------------
// main fused kernel
// ---------------------------------------------------------------------------
__global__ void __launch_bounds__(512, 1)
stress_mlp(const float* __restrict__ Fg, const float* __restrict__ Cg,
           const float* __restrict__ W1,
           const float* __restrict__ W2, const float* __restrict__ b2,
           const float* __restrict__ W3, const float* __restrict__ b3,
           const float* __restrict__ W4, const float* __restrict__ b4,
           const float* __restrict__ W5, const float* __restrict__ b5,
           float* __restrict__ out) {
    extern __shared__ float sm[];
    float* sA   = sm;                       // [128][264] activations / feats
    float* wbuf = sm + SA_F;                // 2 x [32][260] weight chunks
    float* sR   = sm + SA_F + WBUF_F;       // [128][9] polar rotation
    float* sF   = sR + SR_F;                // [128][9] F
    float* sW5  = sF + SF_F;                // [256*9]

    const int tid  = threadIdx.x;
    const int m0   = blockIdx.x * MTILE;
    const int warp = tid >> 5, lane = tid & 31;
    const int wm = warp >> 2, wn = warp & 3;
    const int g  = lane >> 2, t  = lane & 3;

    // ---------------- prologue (threads 0..127) + staging (128..511) -------
    if (tid < MTILE) {
        const int r  = tid;
        const int gr = m0 + r;
        float f[9], c9[9];
#pragma unroll
        for (int i = 0; i < 9; ++i) { f[i] = Fg[gr * 9 + i]; c9[i] = Cg[gr * 9 + i]; }

        // G = F^T F (row-major F: F[i][j] = f[3i+j])
        const float g00 = f[0]*f[0] + f[3]*f[3] + f[6]*f[6];
        const float g01 = f[0]*f[1] + f[3]*f[4] + f[6]*f[7];
        const float g02 = f[0]*f[2] + f[3]*f[5] + f[6]*f[8];
        const float g11 = f[1]*f[1] + f[4]*f[4] + f[7]*f[7];
        const float g12 = f[1]*f[2] + f[4]*f[5] + f[7]*f[8];
        const float g22 = f[2]*f[2] + f[5]*f[5] + f[8]*f[8];
        const float det = f[0]*(f[4]*f[8] - f[5]*f[7])
                        - f[1]*(f[3]*f[8] - f[5]*f[6])
                        + f[2]*(f[3]*f[7] - f[4]*f[6]);

        // symmetric 3x3 eigenvalues (descending) -> singular values of F
        const float q3 = (g00 + g11 + g22) * (1.0f / 3.0f);
        const float d0 = g00 - q3, d1 = g11 - q3, d2 = g22 - q3;
        const float p1 = g01*g01 + g02*g02 + g12*g12;
        const float p2 = d0*d0 + d1*d1 + d2*d2 + 2.0f * p1;
        float l1, l2, l3;
        if (p2 < 1e-30f) { l1 = l2 = l3 = q3; }
        else {
            const float p  = sqrtf(p2 * (1.0f / 6.0f));
            const float ip = 1.0f / p;
            const float b00 = d0*ip, b11 = d1*ip, b22 = d2*ip;
            const float b01 = g01*ip, b02 = g02*ip, b12 = g12*ip;
            const float detB = b00*(b11*b22 - b12*b12)
                             - b01*(b01*b22 - b12*b02)
                             + b02*(b01*b12 - b11*b02);
            const float rr  = fminf(fmaxf(0.5f * detB, -1.0f), 1.0f);
            const float phi = acosf(rr) * (1.0f / 3.0f);
            l1 = q3 + 2.0f * p * cosf(phi);
            l3 = q3 + 2.0f * p * cosf(phi + 2.0943951023931953f);
            l2 = 3.0f * q3 - l1 - l3;
        }
        const float s1 = sqrtf(fmaxf(l1, 0.0f));
        const float s2 = sqrtf(fmaxf(l2, 0.0f));
        const float s3 = sqrtf(fmaxf(l3, 0.0f));

        // polar rotation R = U V^T via Newton: R <- 0.5 (R + R^{-T})
        float R9[9];
#pragma unroll
        for (int i = 0; i < 9; ++i) R9[i] = f[i];
#pragma unroll
        for (int it = 0; it < 5; ++it) {
            const float c00 = R9[4]*R9[8] - R9[5]*R9[7];
            const float c01 = R9[5]*R9[6] - R9[3]*R9[8];
            const float c02 = R9[3]*R9[7] - R9[4]*R9[6];
            const float c10 = R9[2]*R9[7] - R9[1]*R9[8];
            const float c11 = R9[0]*R9[8] - R9[2]*R9[6];
            const float c12 = R9[1]*R9[6] - R9[0]*R9[7];
            const float c20 = R9[1]*R9[5] - R9[2]*R9[4];
            const float c21 = R9[2]*R9[3] - R9[0]*R9[5];
            const float c22 = R9[0]*R9[4] - R9[1]*R9[3];
            const float dd  = R9[0]*c00 + R9[1]*c01 + R9[2]*c02;
            const float h   = 0.5f / dd;
            R9[0] = 0.5f*R9[0] + c00*h;  R9[1] = 0.5f*R9[1] + c01*h;  R9[2] = 0.5f*R9[2] + c02*h;
            R9[3] = 0.5f*R9[3] + c10*h;  R9[4] = 0.5f*R9[4] + c11*h;  R9[5] = 0.5f*R9[5] + c12*h;
            R9[6] = 0.5f*R9[6] + c20*h;  R9[7] = 0.5f*R9[7] + c21*h;  R9[8] = 0.5f*R9[8] + c22*h;
        }

        // feats (normalize_input=True branch)
        float* fr = &sA[r * LDA];
        fr[0] = s1 - 1.0f; fr[1] = s2 - 1.0f; fr[2] = s3 - 1.0f;
        fr[3] = g00 - 1.0f; fr[4] = g01;        fr[5]  = g02;
        fr[6] = g01;        fr[7] = g11 - 1.0f; fr[8]  = g12;
        fr[9] = g02;        fr[10] = g12;       fr[11] = g22 - 1.0f;
        fr[12] = det - 1.0f;
        fr[13] = logf(det) - 1.0f;
        const float f00 = fmaxf(f[0], 1e-6f);
        fr[14] = f00 - 1.0f;
        fr[15] = logf(f00) - 1.0f;
#pragma unroll
        for (int i = 0; i < 9; ++i) fr[16 + i] = c9[i];
#pragma unroll
        for (int i = 25; i < 32; ++i) fr[i] = 0.0f;   // K padding for layer-1
#pragma unroll
        for (int i = 0; i < 9; ++i) { sR[r * 9 + i] = R9[i]; sF[r * 9 + i] = f[i]; }
    } else {
        const int lt = tid - MTILE;   // 0..383
        // W1a (rows 0..24 of W1, zero-padded to 32 rows) -> wbuf[0]
        for (int e = lt; e < 32 * NH; e += 384) {
            const int kk = e >> 8, n = e & 255;
            wbuf[kk * LDW + n] = (kk < 25) ? W1[kk * NH + n] : 0.0f;
        }
        // W5 -> smem
        for (int e = lt; e < NH * 9; e += 384) sW5[e] = W5[e];
    }
    __syncthreads();

    // ---------------- layer 1 (K=32, weights already staged) ---------------
    {
        float acc[2][8][4];
#pragma unroll
        for (int mt = 0; mt < 2; ++mt)
#pragma unroll
            for (int nt = 0; nt < 8; ++nt)
#pragma unroll
                for (int i = 0; i < 4; ++i) acc[mt][nt][i] = 0.0f;
        mma_chunk(sA, 0, wbuf, acc, wm, wn, g, t);
        __syncthreads();
        epilogue_gelu(acc, g_base1, sA, wm, wn, g, t);
        __syncthreads();
    }

    // ---------------- layers 2..4 (K=256, streamed weights) ----------------
    run_layer(W2, b2, sA, wbuf, tid, wm, wn, g, t);
    run_layer(W3, b3, sA, wbuf, tid, wm, wn, g, t);
    run_layer(W4, b4, sA, wbuf, tid, wm, wn, g, t);

    // ---------------- layer 5 + stress epilogue ----------------------------
    {
        const int row = tid >> 2, q = tid & 3;   // 4 threads per row split K
        float a9[9] = {0, 0, 0, 0, 0, 0, 0, 0, 0};
#pragma unroll 4
        for (int i = 0; i < 64; ++i) {
            const int k = (i << 2) + q;
            const float a = sA[row * LDA + k];
#pragma unroll
            for (int j = 0; j < 9; ++j) a9[j] = fmaf(a, sW5[k * 9 + j], a9[j]);
        }
#pragma unroll
        for (int j = 0; j < 9; ++j) {
            a9[j] += __shfl_xor_sync(0xffffffffu, a9[j], 1);
            a9[j] += __shfl_xor_sync(0xffffffffu, a9[j], 2);
        }
        if (q == 0) {
            float x[9];
#pragma unroll
            for (int j = 0; j < 9; ++j) x[j] = a9[j] + __ldg(&b5[j]);
            // symmetrize
            float S[9];
            S[0] = x[0]; S[4] = x[4]; S[8] = x[8];
            S[1] = S[3] = 0.5f * (x[1] + x[3]);
            S[2] = S[6] = 0.5f * (x[2] + x[6]);
            S[5] = S[7] = 0.5f * (x[5] + x[7]);
            float R[9], Fv[9];
#pragma unroll
            for (int i = 0; i < 9; ++i) { R[i] = sR[row * 9 + i]; Fv[i] = sF[row * 9 + i]; }
            float P[9];
#pragma unroll
            for (int i = 0; i < 3; ++i)
#pragma unroll
                for (int j = 0; j < 3; ++j)
                    P[3 * i + j] = R[3 * i] * S[j] + R[3 * i + 1] * S[3 + j] + R[3 * i + 2] * S[6 + j];
            float* o = out + (size_t)(m0 + row) * 9;
#pragma unroll
            for (int i = 0; i < 3; ++i)
#pragma unroll
                for (int j = 0; j < 3; ++j)
                    o[3 * i + j] = P[3 * i] * Fv[3 * j] + P[3 * i + 1] * Fv[3 * j + 1] + P[3 * i + 2] * Fv[3 * j + 2];
        }
    }
}

// ---------------------------------------------------------------------------
// launch
// ---------------------------------------------------------------------------
extern "C" void kernel_launch(void* const* d_in, const int* in_sizes, int n_in,
                              void* d_out, int out_size) {
    const float* F   = (const float*)d_in[0];
    const float* C   = (const float*)d_in[1];
    const float* emb = (const float*)d_in[2];
    const int*   traj = nullptr;
    int base = 3;
    if (n_in >= 14) { traj = (const int*)d_in[3]; base = 4; }  // robust if traj folded out
    const float* W1 = (const float*)d_in[base + 0];
    const float* b1 = (const float*)d_in[base + 1];
    const float* W2 = (const float*)d_in[base + 2];
    const float* b2 = (const float*)d_in[base + 3];
    const float* W3 = (const float*)d_in[base + 4];
    const float* b3 = (const float*)d_in[base + 5];
    const float* W4 = (const float*)d_in[base + 6];
    const float* b4 = (const float*)d_in[base + 7];
    const float* W5 = (const float*)d_in[base + 8];
    const float* b5 = (const float*)d_in[base + 9];
    float* out = (float*)d_out;

    const int B = in_sizes[0] / 9;

    base1_kernel<<<1, 256>>>(emb, traj, W1, b1);

    const int smem_bytes = SMEM_F * (int)sizeof(float);   // 220160 B
    cudaFuncSetAttribute(stress_mlp, cudaFuncAttributeMaxDynamicSharedMemorySize, smem_bytes);
    stress_mlp<<<B / MTILE, 512, smem_bytes>>>(F, C, W1, W2, b2, W3, b3, W4, b4, W5, b5, out);
}

// round 5
// speedup vs baseline: 1.0400x; 1.0400x over previous
#include <cuda_runtime.h>
#include <cstdint>

// ---------------------------------------------------------------------------
// StressNNEval: fused SVD-invariants + 5-layer MLP (erf GELU) + stress epilogue
// R5: all fp32->tf32 conversions hoisted out of the MMA inner loop.
//     Weights pre-rounded to tf32 bits in a prep kernel; activations stored
//     as tf32 bits by the GELU epilogue. Inner loop = LDS + HMMA only.
// ---------------------------------------------------------------------------
#define MTILE   128          // rows per CTA
#define NH      256          // hidden width
#define LDA     264          // smem activation row stride (floats), conflict-free
#define LDW     260          // smem weight-chunk row stride (floats), conflict-free
#define KCHUNK  32           // K streamed per weight chunk
#define WCH_F   (KCHUNK*LDW) // floats per weight chunk buffer = 8320

#define SA_F    (MTILE*LDA)          // 33792
#define WBUF_F  (2*WCH_F)            // 16640
#define SR_F    (MTILE*9)            // 1152
#define SF_F    (MTILE*9)            // 1152
#define SW5_F   (NH*9)               // 2304
#define SMEM_F  (SA_F + WBUF_F + SR_F + SF_F + SW5_F)   // 55040 floats = 220160 B

__device__ __align__(16) float g_base1[NH];
__device__ __align__(16) float g_W1a[32 * NH];   // tf32 bits, rows 0..24 of W1, zero-padded
__device__ __align__(16) float g_W2c[NH * NH];   // tf32 bits
__device__ __align__(16) float g_W3c[NH * NH];
__device__ __align__(16) float g_W4c[NH * NH];

// ---------------------------------------------------------------------------
// helpers
// ---------------------------------------------------------------------------
__device__ __forceinline__ uint32_t f2tf(float x) {
    uint32_t r;
    asm("cvt.rna.tf32.f32 %0, %1;" : "=r"(r) : "f"(x));
    return r;
}
__device__ __forceinline__ float f2tf_f(float x) { return __uint_as_float(f2tf(x)); }

__device__ __forceinline__ void mma8(float c[4], const uint32_t a[4], const uint32_t b[2]) {
    asm volatile(
        "mma.sync.aligned.m16n8k8.row.col.f32.tf32.tf32.f32 "
        "{%0,%1,%2,%3},{%4,%5,%6,%7},{%8,%9},{%0,%1,%2,%3};\n"
        : "+f"(c[0]), "+f"(c[1]), "+f"(c[2]), "+f"(c[3])
        : "r"(a[0]), "r"(a[1]), "r"(a[2]), "r"(a[3]), "r"(b[0]), "r"(b[1]));
}

__device__ __forceinline__ void cp16(float* s, const float* g) {
    uint32_t sa = (uint32_t)__cvta_generic_to_shared(s);
    asm volatile("cp.async.cg.shared.global [%0], [%1], 16;\n" :: "r"(sa), "l"(g));
}
__device__ __forceinline__ void cp_commit() { asm volatile("cp.async.commit_group;\n"); }
__device__ __forceinline__ void cp_wait0()  { asm volatile("cp.async.wait_group 0;\n"); }
__device__ __forceinline__ void cp_wait1()  { asm volatile("cp.async.wait_group 1;\n"); }

__device__ __forceinline__ float gelu_f(float x) {
    // exact (erf) GELU matching jax.nn.gelu(approximate=False)
    return 0.5f * x * (1.0f + erff(x * 0.70710678118654752f));
}

// ---------------------------------------------------------------------------
// one 32-wide K chunk of the 128x256 GEMM (tf32 mma.sync, 16 warps: 4x4 grid)
// sA and wch hold PRE-ROUNDED tf32 bit patterns -> no cvt in the loop.
// K-permutation inside each k8: slot t -> k=2t, slot t+4 -> k=2t+1 (A and B
// use the same permutation -> result unchanged; enables LDS.64 A loads)
// ---------------------------------------------------------------------------
__device__ __forceinline__ void mma_chunk(const float* __restrict__ sAf, int kA,
                                          const float* __restrict__ wchf,
                                          float acc[2][8][4],
                                          int wm, int wn, int g, int t) {
    const uint32_t* __restrict__ sA  = (const uint32_t*)sAf;
    const uint32_t* __restrict__ wch = (const uint32_t*)wchf;
#pragma unroll
    for (int k8 = 0; k8 < 4; ++k8) {
        const int kk = k8 * 8;
        uint32_t a[2][4];
#pragma unroll
        for (int mt = 0; mt < 2; ++mt) {
            const int row = wm * 32 + mt * 16 + g;
            const uint2 lo = *(const uint2*)&sA[row * LDA + kA + kk + 2 * t];
            const uint2 hi = *(const uint2*)&sA[(row + 8) * LDA + kA + kk + 2 * t];
            a[mt][0] = lo.x; a[mt][2] = lo.y;
            a[mt][1] = hi.x; a[mt][3] = hi.y;
        }
        uint32_t b[8][2];
#pragma unroll
        for (int nt = 0; nt < 8; ++nt) {
            const int col = wn * 64 + nt * 8 + g;
            b[nt][0] = wch[(kk + 2 * t)     * LDW + col];
            b[nt][1] = wch[(kk + 2 * t + 1) * LDW + col];
        }
#pragma unroll
        for (int mt = 0; mt < 2; ++mt)
#pragma unroll
            for (int nt = 0; nt < 8; ++nt)
                mma8(acc[mt][nt], a[mt], b[nt]);
    }
}

// GELU(acc+bias) -> sA as tf32 bit patterns (ready for next layer's A loads)
__device__ __forceinline__ void epilogue_gelu(float acc[2][8][4],
                                              const float* __restrict__ bias,
                                              float* __restrict__ sA,
                                              int wm, int wn, int g, int t) {
#pragma unroll
    for (int nt = 0; nt < 8; ++nt) {
        const int col = wn * 64 + nt * 8 + 2 * t;
        const float2 bb = *(const float2*)&bias[col];
#pragma unroll
        for (int mt = 0; mt < 2; ++mt) {
            const int row = wm * 32 + mt * 16 + g;
            float2 v0, v1;
            v0.x = f2tf_f(gelu_f(acc[mt][nt][0] + bb.x));
            v0.y = f2tf_f(gelu_f(acc[mt][nt][1] + bb.y));
            v1.x = f2tf_f(gelu_f(acc[mt][nt][2] + bb.x));
            v1.y = f2tf_f(gelu_f(acc[mt][nt][3] + bb.y));
            *(float2*)&sA[row * LDA + col]       = v0;
            *(float2*)&sA[(row + 8) * LDA + col] = v1;
        }
    }
}

// async-stage weight chunk c (32 rows x 256 cols, already tf32 bits) into smem
__device__ __forceinline__ void stage_w(float* __restrict__ dst,
                                        const float* __restrict__ Wg,
                                        int chunk, int tid) {
    const float* src = Wg + chunk * KCHUNK * NH;
#pragma unroll
    for (int i = 0; i < 4; ++i) {
        const int e  = tid + i * 512;   // 0..2047 float4s
        const int kk = e >> 6;
        const int n4 = (e & 63) << 2;
        cp16(&dst[kk * LDW + n4], &src[kk * NH + n4]);
    }
}

// one streamed layer: acc = sA[128x256] @ W[256x256]; GELU(acc+bias) -> sA
__device__ __forceinline__ void run_layer(const float* __restrict__ Wg,
                                          const float* __restrict__ bias,
                                          float* __restrict__ sA,
                                          float* __restrict__ wbuf,
                                          int tid, int wm, int wn, int g, int t) {
    float acc[2][8][4];
#pragma unroll
    for (int mt = 0; mt < 2; ++mt)
#pragma unroll
        for (int nt = 0; nt < 8; ++nt)
#pragma unroll
            for (int i = 0; i < 4; ++i) acc[mt][nt][i] = 0.0f;

    stage_w(wbuf, Wg, 0, tid);
    cp_commit();
#pragma unroll 1
    for (int c = 0; c < 8; ++c) {
        if (c < 7) {
            stage_w(wbuf + ((c + 1) & 1) * WCH_F, Wg, c + 1, tid);
            cp_commit();
            cp_wait1();           // chunk c complete
        } else {
            cp_wait0();
        }
        __syncthreads();          // chunk c visible to all threads
        mma_chunk(sA, c * KCHUNK, wbuf + (c & 1) * WCH_F, acc, wm, wn, g, t);
        __syncthreads();          // reads of buf (c&1) done before chunk c+2 overwrites
    }
    epilogue_gelu(acc, bias, sA, wm, wn, g, t);
    __syncthreads();
}

// ---------------------------------------------------------------------------
// prep: pre-round W2/W3/W4 to tf32 bits; build padded tf32 W1[0:25] block
// ---------------------------------------------------------------------------
__global__ void prep_weights(const float* __restrict__ W1,
                             const float* __restrict__ W2,
                             const float* __restrict__ W3,
                             const float* __restrict__ W4) {
    const int i = blockIdx.x * 256 + threadIdx.x;   // grid 256 -> 65536
    g_W2c[i] = f2tf_f(W2[i]);
    g_W3c[i] = f2tf_f(W3[i]);
    g_W4c[i] = f2tf_f(W4[i]);
    if (i < 32 * NH)
        g_W1a[i] = (i < 25 * NH) ? f2tf_f(W1[i]) : 0.0f;
}

// precompute base1 = b1 + emb[traj] @ W1[25:153, :]
__global__ void base1_kernel(const float* __restrict__ emb,
                             const int* __restrict__ traj,
                             const float* __restrict__ W1,
                             const float* __restrict__ b1) {
    const int n  = threadIdx.x;            // 0..255
    const int tr = traj ? traj[0] : 3;
    float s = b1[n];
    const float* e = emb + tr * 128;
#pragma unroll 8
    for (int d = 0; d < 128; ++d)
        s = fmaf(e[d], W1[(25 + d) * NH + n], s);
    g_base1[n] = s;
}

// ---------------------------------------------------------------------------
// main fused kernel
// ---------------------------------------------------------------------------
__global__ void __launch_bounds__(512, 1)
stress_mlp(const float* __restrict__ Fg, const float* __restrict__ Cg,
           const float* __restrict__ b2,
           const float* __restrict__ b3,
           const float* __restrict__ b4,
           const float* __restrict__ W5, const float* __restrict__ b5,
           float* __restrict__ out) {
    extern __shared__ float sm[];
    float* sA   = sm;                       // [128][264] activations (tf32 bits)
    float* wbuf = sm + SA_F;                // 2 x [32][260] weight chunks (tf32 bits)
    float* sR   = sm + SA_F + WBUF_F;       // [128][9] polar rotation
    float* sF   = sR + SR_F;                // [128][9] F
    float* sW5  = sF + SF_F;                // [256*9] fp32

    const int tid  = threadIdx.x;
    const int m0   = blockIdx.x * MTILE;
    const int warp = tid >> 5, lane = tid & 31;
    const int wm = warp >> 2, wn = warp & 3;
    const int g  = lane >> 2, t  = lane & 3;

    // ---------------- prologue (threads 0..127) + staging (128..511) -------
    if (tid < MTILE) {
        const int r  = tid;
        const int gr = m0 + r;
        float f[9], c9[9];
#pragma unroll
        for (int i = 0; i < 9; ++i) { f[i] = Fg[gr * 9 + i]; c9[i] = Cg[gr * 9 + i]; }

        // G = F^T F (row-major F: F[i][j] = f[3i+j])
        const float g00 = f[0]*f[0] + f[3]*f[3] + f[6]*f[6];
        const float g01 = f[0]*f[1] + f[3]*f[4] + f[6]*f[7];
        const float g02 = f[0]*f[2] + f[3]*f[5] + f[6]*f[8];
        const float g11 = f[1]*f[1] + f[4]*f[4] + f[7]*f[7];
        const float g12 = f[1]*f[2] + f[4]*f[5] + f[7]*f[8];
        const float g22 = f[2]*f[2] + f[5]*f[5] + f[8]*f[8];
        const float det = f[0]*(f[4]*f[8] - f[5]*f[7])
                        - f[1]*(f[3]*f[8] - f[5]*f[6])
                        + f[2]*(f[3]*f[7] - f[4]*f[6]);

        // symmetric 3x3 eigenvalues (descending) -> singular values of F
        const float q3 = (g00 + g11 + g22) * (1.0f / 3.0f);
        const float d0 = g00 - q3, d1 = g11 - q3, d2 = g22 - q3;
        const float p1 = g01*g01 + g02*g02 + g12*g12;
        const float p2 = d0*d0 + d1*d1 + d2*d2 + 2.0f * p1;
        float l1, l2, l3;
        if (p2 < 1e-30f) { l1 = l2 = l3 = q3; }
        else {
            const float p  = sqrtf(p2 * (1.0f / 6.0f));
            const float ip = 1.0f / p;
            const float b00 = d0*ip, b11 = d1*ip, b22 = d2*ip;
            const float b01 = g01*ip, b02 = g02*ip, b12 = g12*ip;
            const float detB = b00*(b11*b22 - b12*b12)
                             - b01*(b01*b22 - b12*b02)
                             + b02*(b01*b12 - b11*b02);
            const float rr  = fminf(fmaxf(0.5f * detB, -1.0f), 1.0f);
            const float phi = acosf(rr) * (1.0f / 3.0f);
            l1 = q3 + 2.0f * p * cosf(phi);
            l3 = q3 + 2.0f * p * cosf(phi + 2.0943951023931953f);
            l2 = 3.0f * q3 - l1 - l3;
        }
        const float s1 = sqrtf(fmaxf(l1, 0.0f));
        const float s2 = sqrtf(fmaxf(l2, 0.0f));
        const float s3 = sqrtf(fmaxf(l3, 0.0f));

        // polar rotation R = U V^T via Newton: R <- 0.5 (R + R^{-T})
        float R9[9];
#pragma unroll
        for (int i = 0; i < 9; ++i) R9[i] = f[i];
#pragma unroll
        for (int it = 0; it < 5; ++it) {
            const float c00 = R9[4]*R9[8] - R9[5]*R9[7];
            const float c01 = R9[5]*R9[6] - R9[3]*R9[8];
            const float c02 = R9[3]*R9[7] - R9[4]*R9[6];
            const float c10 = R9[2]*R9[7] - R9[1]*R9[8];
            const float c11 = R9[0]*R9[8] - R9[2]*R9[6];
            const float c12 = R9[1]*R9[6] - R9[0]*R9[7];
            const float c20 = R9[1]*R9[5] - R9[2]*R9[4];
            const float c21 = R9[2]*R9[3] - R9[0]*R9[5];
            const float c22 = R9[0]*R9[4] - R9[1]*R9[3];
            const float dd  = R9[0]*c00 + R9[1]*c01 + R9[2]*c02;
            const float h   = 0.5f / dd;
            R9[0] = 0.5f*R9[0] + c00*h;  R9[1] = 0.5f*R9[1] + c01*h;  R9[2] = 0.5f*R9[2] + c02*h;
            R9[3] = 0.5f*R9[3] + c10*h;  R9[4] = 0.5f*R9[4] + c11*h;  R9[5] = 0.5f*R9[5] + c12*h;
            R9[6] = 0.5f*R9[6] + c20*h;  R9[7] = 0.5f*R9[7] + c21*h;  R9[8] = 0.5f*R9[8] + c22*h;
        }

        // feats (normalize_input=True branch) stored as tf32 bits
        float* fr = &sA[r * LDA];
        fr[0] = f2tf_f(s1 - 1.0f); fr[1] = f2tf_f(s2 - 1.0f); fr[2] = f2tf_f(s3 - 1.0f);
        fr[3] = f2tf_f(g00 - 1.0f); fr[4]  = f2tf_f(g01);        fr[5]  = f2tf_f(g02);
        fr[6] = f2tf_f(g01);        fr[7]  = f2tf_f(g11 - 1.0f); fr[8]  = f2tf_f(g12);
        fr[9] = f2tf_f(g02);        fr[10] = f2tf_f(g12);        fr[11] = f2tf_f(g22 - 1.0f);
        fr[12] = f2tf_f(det - 1.0f);
        fr[13] = f2tf_f(logf(det) - 1.0f);
        const float f00 = fmaxf(f[0], 1e-6f);
        fr[14] = f2tf_f(f00 - 1.0f);
        fr[15] = f2tf_f(logf(f00) - 1.0f);
#pragma unroll
        for (int i = 0; i < 9; ++i) fr[16 + i] = f2tf_f(c9[i]);
#pragma unroll
        for (int i = 25; i < 32; ++i) fr[i] = 0.0f;   // K padding for layer-1
#pragma unroll
        for (int i = 0; i < 9; ++i) { sR[r * 9 + i] = R9[i]; sF[r * 9 + i] = f[i]; }
    } else {
        const int lt = tid - MTILE;   // 0..383
        // W1a (pre-converted + padded tf32 bits) -> wbuf[0]
        for (int e = lt; e < 32 * 64; e += 384) {
            const int kk = e >> 6, n4 = (e & 63) << 2;
            *(float4*)&wbuf[kk * LDW + n4] = *(const float4*)&g_W1a[kk * NH + n4];
        }
        // W5 (fp32) -> smem
        for (int e = lt; e < NH * 9; e += 384) sW5[e] = W5[e];
    }
    __syncthreads();

    // ---------------- layer 1 (K=32, weights already staged) ---------------
    {
        float acc[2][8][4];
#pragma unroll
        for (int mt = 0; mt < 2; ++mt)
#pragma unroll
            for (int nt = 0; nt < 8; ++nt)
#pragma unroll
                for (int i = 0; i < 4; ++i) acc[mt][nt][i] = 0.0f;
        mma_chunk(sA, 0, wbuf, acc, wm, wn, g, t);
        __syncthreads();
        epilogue_gelu(acc, g_base1, sA, wm, wn, g, t);
        __syncthreads();
    }

    // ---------------- layers 2..4 (K=256, streamed pre-converted weights) --
    run_layer(g_W2c, b2, sA, wbuf, tid, wm, wn, g, t);
    run_layer(g_W3c, b3, sA, wbuf, tid, wm, wn, g, t);
    run_layer(g_W4c, b4, sA, wbuf, tid, wm, wn, g, t);

    // ---------------- layer 5 + stress epilogue ----------------------------
    {
        const int row = tid >> 2, q = tid & 3;   // 4 threads per row split K
        float a9[9] = {0, 0, 0, 0, 0, 0, 0, 0, 0};
#pragma unroll 4
        for (int i = 0; i < 64; ++i) {
            const int k = (i << 2) + q;
            const float a = sA[row * LDA + k];
#pragma unroll
            for (int j = 0; j < 9; ++j) a9[j] = fmaf(a, sW5[k * 9 + j], a9[j]);
        }
#pragma unroll
        for (int j = 0; j < 9; ++j) {
            a9[j] += __shfl_xor_sync(0xffffffffu, a9[j], 1);
            a9[j] += __shfl_xor_sync(0xffffffffu, a9[j], 2);
        }
        if (q == 0) {
            float x[9];
#pragma unroll
            for (int j = 0; j < 9; ++j) x[j] = a9[j] + __ldg(&b5[j]);
            // symmetrize
            float S[9];
            S[0] = x[0]; S[4] = x[4]; S[8] = x[8];
            S[1] = S[3] = 0.5f * (x[1] + x[3]);
            S[2] = S[6] = 0.5f * (x[2] + x[6]);
            S[5] = S[7] = 0.5f * (x[5] + x[7]);
            float R[9], Fv[9];
#pragma unroll
            for (int i = 0; i < 9; ++i) { R[i] = sR[row * 9 + i]; Fv[i] = sF[row * 9 + i]; }
            float P[9];
#pragma unroll
            for (int i = 0; i < 3; ++i)
#pragma unroll
                for (int j = 0; j < 3; ++j)
                    P[3 * i + j] = R[3 * i] * S[j] + R[3 * i + 1] * S[3 + j] + R[3 * i + 2] * S[6 + j];
            float* o = out + (size_t)(m0 + row) * 9;
#pragma unroll
            for (int i = 0; i < 3; ++i)
#pragma unroll
                for (int j = 0; j < 3; ++j)
                    o[3 * i + j] = P[3 * i] * Fv[3 * j] + P[3 * i + 1] * Fv[3 * j + 1] + P[3 * i + 2] * Fv[3 * j + 2];
        }
    }
}

// ---------------------------------------------------------------------------
// launch
// ---------------------------------------------------------------------------
extern "C" void kernel_launch(void* const* d_in, const int* in_sizes, int n_in,
                              void* d_out, int out_size) {
    const float* F   = (const float*)d_in[0];
    const float* C   = (const float*)d_in[1];
    const float* emb = (const float*)d_in[2];
    const int*   traj = nullptr;
    int base = 3;
    if (n_in >= 14) { traj = (const int*)d_in[3]; base = 4; }
    const float* W1 = (const float*)d_in[base + 0];
    const float* b1 = (const float*)d_in[base + 1];
    const float* W2 = (const float*)d_in[base + 2];
    const float* b2 = (const float*)d_in[base + 3];
    const float* W3 = (const float*)d_in[base + 4];
    const float* b3 = (const float*)d_in[base + 5];
    const float* W4 = (const float*)d_in[base + 6];
    const float* b4 = (const float*)d_in[base + 7];
    const float* W5 = (const float*)d_in[base + 8];
    const float* b5 = (const float*)d_in[base + 9];
    float* out = (float*)d_out;

    const int B = in_sizes[0] / 9;

    prep_weights<<<NH * NH / 256, 256>>>(W1, W2, W3, W4);
    base1_kernel<<<1, 256>>>(emb, traj, W1, b1);

    const int smem_bytes = SMEM_F * (int)sizeof(float);   // 220160 B
    cudaFuncSetAttribute(stress_mlp, cudaFuncAttributeMaxDynamicSharedMemorySize, smem_bytes);
    stress_mlp<<<B / MTILE, 512, smem_bytes>>>(F, C, b2, b3, b4, W5, b5, out);
}

// round 6
// speedup vs baseline: 1.6541x; 1.5905x over previous
#include <cuda_runtime.h>
#include <cuda_fp16.h>
#include <cstdint>

// ---------------------------------------------------------------------------
// StressNNEval R6: fp16 (m16n8k16) GEMM path, fp32 accumulate.
//  - weights pre-packed to half2 k-pairs [k/2][col] in prep kernel
//  - full 256x256 layer weights resident in smem (4 K=64 chunk slots)
//  - 1 barrier per chunk + 1 per layer; next layer's chunk q staged into
//    slot q immediately after chunk q is consumed
//  - activations stored fp16 in smem with a K-pair permutation so A-frags
//    load as single LDS.64 per row (a0,a2 packed)
// ---------------------------------------------------------------------------
#define MTILE 128
#define NH    256
#define LDAH  272          // halves per sA row (256 + 16 pad; 136 words == 8 mod 32)
#define LDWH  528          // halves per weight kp-row (264 words == 8 mod 32)
#define NKP   128          // kp rows per full layer (K=256 / 2)

#define OFF_SA   0
#define SZ_SA    (MTILE*LDAH*2)            // 69632
#define OFF_SW   (OFF_SA + SZ_SA)          // 69632
#define SZ_SW    (NKP*LDWH*2)              // 135168
#define OFF_SR   (OFF_SW + SZ_SW)          // 204800
#define SZ_SR    (MTILE*9*4)               // 4608
#define OFF_SF   (OFF_SR + SZ_SR)          // 209408
#define SZ_SF    (MTILE*9*4)               // 4608
#define OFF_SW5  (OFF_SF + SZ_SF)          // 214016
#define SZ_SW5   (NH*9*4)                  // 9216
#define SMEM_BYTES (OFF_SW5 + SZ_SW5)      // 223232

__device__ __align__(16) float  g_base1[NH];
__device__ __align__(16) __half g_W1h[16 * 512];    // K=32 (25 real, zero-pad), packed pairs
__device__ __align__(16) __half g_W2h[NKP * 512];
__device__ __align__(16) __half g_W3h[NKP * 512];
__device__ __align__(16) __half g_W4h[NKP * 512];

// ---------------------------------------------------------------------------
// helpers
// ---------------------------------------------------------------------------
__device__ __forceinline__ void mma16(float c[4], const uint32_t a[4], const uint32_t b[2]) {
    asm volatile(
        "mma.sync.aligned.m16n8k16.row.col.f32.f16.f16.f32 "
        "{%0,%1,%2,%3},{%4,%5,%6,%7},{%8,%9},{%0,%1,%2,%3};\n"
        : "+f"(c[0]), "+f"(c[1]), "+f"(c[2]), "+f"(c[3])
        : "r"(a[0]), "r"(a[1]), "r"(a[2]), "r"(a[3]), "r"(b[0]), "r"(b[1]));
}

__device__ __forceinline__ void cp16h(__half* s, const __half* g) {
    uint32_t sa = (uint32_t)__cvta_generic_to_shared(s);
    asm volatile("cp.async.cg.shared.global [%0], [%1], 16;\n" :: "r"(sa), "l"(g));
}
__device__ __forceinline__ void cp16f(float* s, const float* g) {
    uint32_t sa = (uint32_t)__cvta_generic_to_shared(s);
    asm volatile("cp.async.cg.shared.global [%0], [%1], 16;\n" :: "r"(sa), "l"(g));
}
__device__ __forceinline__ void cp_commit() { asm volatile("cp.async.commit_group;\n"); }
__device__ __forceinline__ void cp_wait0()  { asm volatile("cp.async.wait_group 0;\n"); }

__device__ __forceinline__ float gelu_f(float x) {
    // exact (erf) GELU matching jax.nn.gelu(approximate=False)
    return 0.5f * x * (1.0f + erff(x * 0.70710678118654752f));
}

// logical k -> half index within an sA row (K-pair permutation: storage
// halves [16g+4q .. 16g+4q+3] hold k {16g+2q, 16g+2q+1, 16g+2q+8, 16g+2q+9})
__device__ __forceinline__ int kmap(int k) {
    const int grp = k >> 4, r = k & 15, p = r >> 1, s = r & 1;
    const int base = (p < 4) ? 4 * p : 4 * (p - 4) + 2;
    return grp * 16 + base + s;
}

// ---------------------------------------------------------------------------
// NKG k16-steps of the 128x256 GEMM from chunk base sWc (kp rows kg*8+t)
// ---------------------------------------------------------------------------
template<int NKG>
__device__ __forceinline__ void mma_chunk_h(const __half* __restrict__ sAh, int kg0,
                                            const __half* __restrict__ sWc,
                                            float acc[2][8][4],
                                            int wm, int wn, int g, int t) {
#pragma unroll
    for (int kg = 0; kg < NKG; ++kg) {
        uint32_t a[2][4];
#pragma unroll
        for (int mt = 0; mt < 2; ++mt) {
            const int row = wm * 32 + mt * 16 + g;
            const uint2 lo = *(const uint2*)&sAh[row * LDAH + (kg0 + kg) * 16 + 4 * t];
            const uint2 hi = *(const uint2*)&sAh[(row + 8) * LDAH + (kg0 + kg) * 16 + 4 * t];
            a[mt][0] = lo.x; a[mt][2] = lo.y;   // (row g,   k 2t..2t+1), (row g,   k 2t+8..)
            a[mt][1] = hi.x; a[mt][3] = hi.y;   // (row g+8, ...)
        }
        const __half* w0 = sWc + (kg * 8 + t) * LDWH;
        const __half* w1 = w0 + 4 * LDWH;
        uint32_t b[8][2];
#pragma unroll
        for (int nt = 0; nt < 8; ++nt) {
            const int col = wn * 64 + nt * 8 + g;
            b[nt][0] = *(const uint32_t*)&w0[col * 2];
            b[nt][1] = *(const uint32_t*)&w1[col * 2];
        }
#pragma unroll
        for (int mt = 0; mt < 2; ++mt)
#pragma unroll
            for (int nt = 0; nt < 8; ++nt)
                mma16(acc[mt][nt], a[mt], b[nt]);
    }
}

// GELU(acc+bias) -> sA as fp16 in the permuted K-pair layout
__device__ __forceinline__ void epilogue_gelu_h(float acc[2][8][4],
                                                const float* __restrict__ bias,
                                                __half* __restrict__ sAh,
                                                int wm, int wn, int g, int t) {
#pragma unroll
    for (int nt = 0; nt < 8; ++nt) {
        const int col  = wn * 64 + nt * 8 + 2 * t;
        const float2 bb = *(const float2*)&bias[col];
        const int hoff = (wn * 4 + (nt >> 1)) * 16 + 4 * t + (nt & 1) * 2;
#pragma unroll
        for (int mt = 0; mt < 2; ++mt) {
            const int row = wm * 32 + mt * 16 + g;
            const __half2 v0 = __floats2half2_rn(gelu_f(acc[mt][nt][0] + bb.x),
                                                 gelu_f(acc[mt][nt][1] + bb.y));
            const __half2 v1 = __floats2half2_rn(gelu_f(acc[mt][nt][2] + bb.x),
                                                 gelu_f(acc[mt][nt][3] + bb.y));
            *(__half2*)&sAh[row * LDAH + hoff]       = v0;
            *(__half2*)&sAh[(row + 8) * LDAH + hoff] = v1;
        }
    }
}

// stage one K=64 chunk (32 kp rows x 512 halves) into smem slot
__device__ __forceinline__ void stage_chunk(__half* __restrict__ dst,
                                            const __half* __restrict__ src, int tid) {
#pragma unroll
    for (int i = 0; i < 4; ++i) {
        const int e  = tid + i * 512;      // 0..2047 16B packets
        const int kk = e >> 6;
        const int n8 = (e & 63) * 8;
        cp16h(&dst[kk * LDWH + n8], &src[kk * 512 + n8]);
    }
}

// one full layer: acc = sA @ W (resident in sW); GELU -> sA; stage Wnext
__device__ __forceinline__ void run_layer_h(const __half* __restrict__ Wnext,
                                            const float* __restrict__ bias,
                                            __half* __restrict__ sAh,
                                            __half* __restrict__ sWh,
                                            int tid, int wm, int wn, int g, int t) {
    float acc[2][8][4];
#pragma unroll
    for (int mt = 0; mt < 2; ++mt)
#pragma unroll
        for (int nt = 0; nt < 8; ++nt)
#pragma unroll
            for (int i = 0; i < 4; ++i) acc[mt][nt][i] = 0.0f;

#pragma unroll 1
    for (int q = 0; q < 4; ++q) {
        mma_chunk_h<4>(sAh, q * 4, sWh + q * 32 * LDWH, acc, wm, wn, g, t);
        __syncthreads();                               // slot q fully consumed
        if (Wnext) { stage_chunk(sWh + q * 32 * LDWH, Wnext + q * 32 * 512, tid); cp_commit(); }
    }
    epilogue_gelu_h(acc, bias, sAh, wm, wn, g, t);
    if (Wnext) cp_wait0();
    __syncthreads();
}

// ---------------------------------------------------------------------------
// prep: pack W2/W3/W4 (and padded W1[0:25]) as half2 k-pairs [k/2][col]
// ---------------------------------------------------------------------------
__global__ void prep_weights_h(const float* __restrict__ W1,
                               const float* __restrict__ W2,
                               const float* __restrict__ W3,
                               const float* __restrict__ W4) {
    const int i = blockIdx.x * 256 + threadIdx.x;   // grid 128 -> 32768 = 128*256
    const int kp = i >> 8, col = i & 255;
    const int k0 = 2 * kp, k1 = 2 * kp + 1;
    ((__half2*)g_W2h)[i] = __floats2half2_rn(W2[k0 * NH + col], W2[k1 * NH + col]);
    ((__half2*)g_W3h)[i] = __floats2half2_rn(W3[k0 * NH + col], W3[k1 * NH + col]);
    ((__half2*)g_W4h)[i] = __floats2half2_rn(W4[k0 * NH + col], W4[k1 * NH + col]);
    if (kp < 16) {
        const float a = (k0 < 25) ? W1[k0 * NH + col] : 0.0f;
        const float b = (k1 < 25) ? W1[k1 * NH + col] : 0.0f;
        ((__half2*)g_W1h)[i] = __floats2half2_rn(a, b);
    }
}

// precompute base1 = b1 + emb[traj] @ W1[25:153, :]   (fp32)
__global__ void base1_kernel(const float* __restrict__ emb,
                             const int* __restrict__ traj,
                             const float* __restrict__ W1,
                             const float* __restrict__ b1) {
    const int n  = threadIdx.x;            // 0..255
    const int tr = traj ? traj[0] : 3;
    float s = b1[n];
    const float* e = emb + tr * 128;
#pragma unroll 8
    for (int d = 0; d < 128; ++d)
        s = fmaf(e[d], W1[(25 + d) * NH + n], s);
    g_base1[n] = s;
}

// ---------------------------------------------------------------------------
// main fused kernel
// ---------------------------------------------------------------------------
__global__ void __launch_bounds__(512, 1)
stress_mlp(const float* __restrict__ Fg, const float* __restrict__ Cg,
           const float* __restrict__ b2,
           const float* __restrict__ b3,
           const float* __restrict__ b4,
           const float* __restrict__ W5, const float* __restrict__ b5,
           float* __restrict__ out) {
    extern __shared__ char smem[];
    __half* sAh = (__half*)(smem + OFF_SA);
    __half* sWh = (__half*)(smem + OFF_SW);
    float*  sR  = (float*)(smem + OFF_SR);
    float*  sF  = (float*)(smem + OFF_SF);
    float*  sW5 = (float*)(smem + OFF_SW5);

    const int tid  = threadIdx.x;
    const int m0   = blockIdx.x * MTILE;
    const int warp = tid >> 5, lane = tid & 31;
    const int wm = warp >> 2, wn = warp & 3;
    const int g  = lane >> 2, t  = lane & 3;

    // ----- issue all prologue cp.async first (W1a, W2 chunks 1..3, W5) -----
#pragma unroll
    for (int i = 0; i < 2; ++i) {
        const int e = tid + i * 512;           // 0..1023
        const int kk = e >> 6, n8 = (e & 63) * 8;
        cp16h(&sWh[kk * LDWH + n8], &g_W1h[kk * 512 + n8]);
    }
    stage_chunk(sWh + 1 * 32 * LDWH, g_W2h + 1 * 32 * 512, tid);
    stage_chunk(sWh + 2 * 32 * LDWH, g_W2h + 2 * 32 * 512, tid);
    stage_chunk(sWh + 3 * 32 * LDWH, g_W3h == nullptr ? g_W2h : g_W2h + 3 * 32 * 512, tid);
    if (tid < 576 - 512) cp16f(&sW5[(tid + 512) * 4], &W5[(tid + 512) * 4]);
    cp16f(&sW5[tid * 4 < 2048 ? tid * 4 : 0], &W5[tid * 4 < 2048 ? tid * 4 : 0]); // tid<512 covers 0..2047
    cp_commit();

    // ---------------- prologue math (threads 0..127) -----------------------
    if (tid < MTILE) {
        const int r  = tid;
        const int gr = m0 + r;
        float f[9], c9[9];
#pragma unroll
        for (int i = 0; i < 9; ++i) { f[i] = Fg[gr * 9 + i]; c9[i] = Cg[gr * 9 + i]; }

        const float g00 = f[0]*f[0] + f[3]*f[3] + f[6]*f[6];
        const float g01 = f[0]*f[1] + f[3]*f[4] + f[6]*f[7];
        const float g02 = f[0]*f[2] + f[3]*f[5] + f[6]*f[8];
        const float g11 = f[1]*f[1] + f[4]*f[4] + f[7]*f[7];
        const float g12 = f[1]*f[2] + f[4]*f[5] + f[7]*f[8];
        const float g22 = f[2]*f[2] + f[5]*f[5] + f[8]*f[8];
        const float det = f[0]*(f[4]*f[8] - f[5]*f[7])
                        - f[1]*(f[3]*f[8] - f[5]*f[6])
                        + f[2]*(f[3]*f[7] - f[4]*f[6]);

        const float q3 = (g00 + g11 + g22) * (1.0f / 3.0f);
        const float d0 = g00 - q3, d1 = g11 - q3, d2 = g22 - q3;
        const float p1 = g01*g01 + g02*g02 + g12*g12;
        const float p2 = d0*d0 + d1*d1 + d2*d2 + 2.0f * p1;
        float l1, l2, l3;
        if (p2 < 1e-30f) { l1 = l2 = l3 = q3; }
        else {
            const float p  = sqrtf(p2 * (1.0f / 6.0f));
            const float ip = 1.0f / p;
            const float b00 = d0*ip, b11 = d1*ip, b22 = d2*ip;
            const float b01 = g01*ip, b02 = g02*ip, b12 = g12*ip;
            const float detB = b00*(b11*b22 - b12*b12)
                             - b01*(b01*b22 - b12*b02)
                             + b02*(b01*b12 - b11*b02);
            const float rr  = fminf(fmaxf(0.5f * detB, -1.0f), 1.0f);
            const float phi = acosf(rr) * (1.0f / 3.0f);
            l1 = q3 + 2.0f * p * cosf(phi);
            l3 = q3 + 2.0f * p * cosf(phi + 2.0943951023931953f);
            l2 = 3.0f * q3 - l1 - l3;
        }
        const float s1 = sqrtf(fmaxf(l1, 0.0f));
        const float s2 = sqrtf(fmaxf(l2, 0.0f));
        const float s3 = sqrtf(fmaxf(l3, 0.0f));

        float R9[9];
#pragma unroll
        for (int i = 0; i < 9; ++i) R9[i] = f[i];
#pragma unroll
        for (int it = 0; it < 5; ++it) {
            const float c00 = R9[4]*R9[8] - R9[5]*R9[7];
            const float c01 = R9[5]*R9[6] - R9[3]*R9[8];
            const float c02 = R9[3]*R9[7] - R9[4]*R9[6];
            const float c10 = R9[2]*R9[7] - R9[1]*R9[8];
            const float c11 = R9[0]*R9[8] - R9[2]*R9[6];
            const float c12 = R9[1]*R9[6] - R9[0]*R9[7];
            const float c20 = R9[1]*R9[5] - R9[2]*R9[4];
            const float c21 = R9[2]*R9[3] - R9[0]*R9[5];
            const float c22 = R9[0]*R9[4] - R9[1]*R9[3];
            const float dd  = R9[0]*c00 + R9[1]*c01 + R9[2]*c02;
            const float h   = 0.5f / dd;
            R9[0] = 0.5f*R9[0] + c00*h;  R9[1] = 0.5f*R9[1] + c01*h;  R9[2] = 0.5f*R9[2] + c02*h;
            R9[3] = 0.5f*R9[3] + c10*h;  R9[4] = 0.5f*R9[4] + c11*h;  R9[5] = 0.5f*R9[5] + c12*h;
            R9[6] = 0.5f*R9[6] + c20*h;  R9[7] = 0.5f*R9[7] + c21*h;  R9[8] = 0.5f*R9[8] + c22*h;
        }

        // feats -> fp16 into permuted sA layout (k 0..24 real, 25..31 zero)
        float fe[25];
        fe[0] = s1 - 1.0f; fe[1] = s2 - 1.0f; fe[2] = s3 - 1.0f;
        fe[3] = g00 - 1.0f; fe[4]  = g01;        fe[5]  = g02;
        fe[6] = g01;        fe[7]  = g11 - 1.0f; fe[8]  = g12;
        fe[9] = g02;        fe[10] = g12;        fe[11] = g22 - 1.0f;
        fe[12] = det - 1.0f;
        fe[13] = logf(det) - 1.0f;
        const float f00 = fmaxf(f[0], 1e-6f);
        fe[14] = f00 - 1.0f;
        fe[15] = logf(f00) - 1.0f;
#pragma unroll
        for (int i = 0; i < 9; ++i) fe[16 + i] = c9[i];
        __half* fr = &sAh[r * LDAH];
#pragma unroll
        for (int k = 0; k < 32; ++k)
            fr[kmap(k)] = __float2half_rn(k < 25 ? fe[k] : 0.0f);
#pragma unroll
        for (int i = 0; i < 9; ++i) { sR[r * 9 + i] = R9[i]; sF[r * 9 + i] = f[i]; }
    }
    cp_wait0();
    __syncthreads();

    // ---------------- layer 1 (K=32 -> 2 k16 steps, slot 0) ----------------
    {
        float acc[2][8][4];
#pragma unroll
        for (int mt = 0; mt < 2; ++mt)
#pragma unroll
            for (int nt = 0; nt < 8; ++nt)
#pragma unroll
                for (int i = 0; i < 4; ++i) acc[mt][nt][i] = 0.0f;
        mma_chunk_h<2>(sAh, 0, sWh, acc, wm, wn, g, t);
        __syncthreads();
        stage_chunk(sWh, g_W2h, tid);      // W2 chunk 0 -> slot 0
        cp_commit();
        epilogue_gelu_h(acc, g_base1, sAh, wm, wn, g, t);
        cp_wait0();
        __syncthreads();
    }

    // ---------------- layers 2..4 ------------------------------------------
    run_layer_h(g_W3h,   b2, sAh, sWh, tid, wm, wn, g, t);
    run_layer_h(g_W4h,   b3, sAh, sWh, tid, wm, wn, g, t);
    run_layer_h(nullptr, b4, sAh, sWh, tid, wm, wn, g, t);

    // ---------------- layer 5 + stress epilogue ----------------------------
    {
        const int row = tid >> 2, q4 = tid & 3;   // 4 threads per row split pairs
        float a9[9] = {0, 0, 0, 0, 0, 0, 0, 0, 0};
#pragma unroll 4
        for (int i = 0; i < 32; ++i) {
            const int p   = (i << 2) + q4;        // logical pair 0..127 -> k = 2p,2p+1
            const int pw  = p & 7;
            const int hoff = (p >> 3) * 16 + ((pw < 4) ? 4 * pw : 4 * (pw - 4) + 2);
            const __half2 h = *(const __half2*)&sAh[row * LDAH + hoff];
            const float a0 = __low2float(h), a1 = __high2float(h);
            const int k0 = 2 * p;
#pragma unroll
            for (int j = 0; j < 9; ++j)
                a9[j] = fmaf(a1, sW5[(k0 + 1) * 9 + j], fmaf(a0, sW5[k0 * 9 + j], a9[j]));
        }
#pragma unroll
        for (int j = 0; j < 9; ++j) {
            a9[j] += __shfl_xor_sync(0xffffffffu, a9[j], 1);
            a9[j] += __shfl_xor_sync(0xffffffffu, a9[j], 2);
        }
        if (q4 == 0) {
            float x[9];
#pragma unroll
            for (int j = 0; j < 9; ++j) x[j] = a9[j] + __ldg(&b5[j]);
            float S[9];
            S[0] = x[0]; S[4] = x[4]; S[8] = x[8];
            S[1] = S[3] = 0.5f * (x[1] + x[3]);
            S[2] = S[6] = 0.5f * (x[2] + x[6]);
            S[5] = S[7] = 0.5f * (x[5] + x[7]);
            float R[9], Fv[9];
#pragma unroll
            for (int i = 0; i < 9; ++i) { R[i] = sR[row * 9 + i]; Fv[i] = sF[row * 9 + i]; }
            float P[9];
#pragma unroll
            for (int i = 0; i < 3; ++i)
#pragma unroll
                for (int j = 0; j < 3; ++j)
                    P[3 * i + j] = R[3 * i] * S[j] + R[3 * i + 1] * S[3 + j] + R[3 * i + 2] * S[6 + j];
            float* o = out + (size_t)(m0 + row) * 9;
#pragma unroll
            for (int i = 0; i < 3; ++i)
#pragma unroll
                for (int j = 0; j < 3; ++j)
                    o[3 * i + j] = P[3 * i] * Fv[3 * j] + P[3 * i + 1] * Fv[3 * j + 1] + P[3 * i + 2] * Fv[3 * j + 2];
        }
    }
}

// ---------------------------------------------------------------------------
// launch
// ---------------------------------------------------------------------------
extern "C" void kernel_launch(void* const* d_in, const int* in_sizes, int n_in,
                              void* d_out, int out_size) {
    const float* F   = (const float*)d_in[0];
    const float* C   = (const float*)d_in[1];
    const float* emb = (const float*)d_in[2];
    const int*   traj = nullptr;
    int base = 3;
    if (n_in >= 14) { traj = (const int*)d_in[3]; base = 4; }
    const float* W1 = (const float*)d_in[base + 0];
    const float* b1 = (const float*)d_in[base + 1];
    const float* W2 = (const float*)d_in[base + 2];
    const float* b2 = (const float*)d_in[base + 3];
    const float* W3 = (const float*)d_in[base + 4];
    const float* b3 = (const float*)d_in[base + 5];
    const float* W4 = (const float*)d_in[base + 6];
    const float* b4 = (const float*)d_in[base + 7];
    const float* W5 = (const float*)d_in[base + 8];
    const float* b5 = (const float*)d_in[base + 9];
    float* out = (float*)d_out;

    const int B = in_sizes[0] / 9;

    prep_weights_h<<<128, 256>>>(W1, W2, W3, W4);
    base1_kernel<<<1, 256>>>(emb, traj, W1, b1);

    cudaFuncSetAttribute(stress_mlp, cudaFuncAttributeMaxDynamicSharedMemorySize, SMEM_BYTES);
    stress_mlp<<<B / MTILE, 512, SMEM_BYTES>>>(F, C, b2, b3, b4, W5, b5, out);
}

// round 12
// speedup vs baseline: 2.1876x; 1.3226x over previous
#include <cuda_runtime.h>
#include <cuda_fp16.h>
#include <cstdint>

// ---------------------------------------------------------------------------
// StressNNEval R8: fp16 m16n8k16 + ldmatrix fragments + QUADRATIC GELU LUT.
//  - A (activations) natural [m][k] fp16, stride 264 halfs (LDSM conflict-free)
//  - W natural [n][k] fp16, stride 264 halfs; full layer resident; k-chunked
//    staging of next layer into consumed chunk slots (5 barriers/layer)
//  - GELU: 512-bin per-bin quadratic fit of exact erf-GELU over [-8,8]
//    (max err ~5e-7, unbiased at fp16 scale; fixes R7's chord-bias regression)
// ---------------------------------------------------------------------------
#define MTILE 128
#define NH    256
#define LDAH  264           // halfs per sA row   (132 words == 4 mod 32)
#define LDWH  264           // halfs per sW n-row (132 words == 4 mod 32)

#define OFF_SA   0
#define SZ_SA    (MTILE*LDAH*2)            // 67584
#define OFF_SW   (OFF_SA + SZ_SA)
#define SZ_SW    (NH*LDWH*2)               // 135168
#define OFF_SR   (OFF_SW + SZ_SW)          // 202752
#define SZ_SR    (MTILE*9*4)
#define OFF_SF   (OFF_SR + SZ_SR)
#define SZ_SF    (MTILE*9*4)
#define OFF_SW5  (OFF_SF + SZ_SF)          // 211968
#define SZ_SW5   (NH*9*4)                  // 9216
#define OFF_LUT  (OFF_SW5 + SZ_SW5)        // 221184
#define SZ_LUT   (512*16)                  // 8192
#define SMEM_BYTES (OFF_LUT + SZ_LUT)      // 229376

#define GLO    (-8.0f)
#define GBINS  512
#define GSCALE 32.0f                       // 512 / 16
#define GDX    0.03125f                    // 16 / 512

__device__ __align__(16) float  g_base1[NH];
__device__ __align__(16) __half g_W1h[NH * 32];     // [n][k], k 0..24 real, pad 0
__device__ __align__(16) __half g_W2h[NH * NH];     // [n][k]
__device__ __align__(16) __half g_W3h[NH * NH];
__device__ __align__(16) __half g_W4h[NH * NH];

// ---------------------------------------------------------------------------
// helpers
// ---------------------------------------------------------------------------
__device__ __forceinline__ void mma16(float c[4], const uint32_t a[4], const uint32_t b[2]) {
    asm volatile(
        "mma.sync.aligned.m16n8k16.row.col.f32.f16.f16.f32 "
        "{%0,%1,%2,%3},{%4,%5,%6,%7},{%8,%9},{%0,%1,%2,%3};\n"
        : "+f"(c[0]), "+f"(c[1]), "+f"(c[2]), "+f"(c[3])
        : "r"(a[0]), "r"(a[1]), "r"(a[2]), "r"(a[3]), "r"(b[0]), "r"(b[1]));
}

__device__ __forceinline__ void ldsm4(uint32_t r[4], uint32_t addr) {
    asm volatile("ldmatrix.sync.aligned.m8n8.x4.shared.b16 {%0,%1,%2,%3}, [%4];"
        : "=r"(r[0]), "=r"(r[1]), "=r"(r[2]), "=r"(r[3]) : "r"(addr));
}

__device__ __forceinline__ void cp16h(__half* s, const __half* g) {
    uint32_t sa = (uint32_t)__cvta_generic_to_shared(s);
    asm volatile("cp.async.cg.shared.global [%0], [%1], 16;\n" :: "r"(sa), "l"(g));
}
__device__ __forceinline__ void cp16f(float* s, const float* g) {
    uint32_t sa = (uint32_t)__cvta_generic_to_shared(s);
    asm volatile("cp.async.cg.shared.global [%0], [%1], 16;\n" :: "r"(sa), "l"(g));
}
__device__ __forceinline__ void cp_commit() { asm volatile("cp.async.commit_group;\n"); }
__device__ __forceinline__ void cp_wait0()  { asm volatile("cp.async.wait_group 0;\n"); }

__device__ __forceinline__ float gelu_exact(float x) {
    return 0.5f * x * (1.0f + erff(x * 0.70710678118654752f));
}
// quadratic LUT: c = (xm, a2, a1, a0); y = a0 + a1*u + a2*u^2, u = x - xm
__device__ __forceinline__ float gelu_lut(float x, const float4* __restrict__ lut) {
    int idx = __float2int_rd((x - GLO) * GSCALE);
    idx = max(0, min(idx, GBINS - 1));
    const float4 c = lut[idx];
    const float u = x - c.x;
    return fmaf(fmaf(c.y, u, c.z), u, c.w);
}

// ---------------------------------------------------------------------------
// NKG k16-steps: all fragments via ldmatrix.x4 (addresses are lane-resolved)
// ---------------------------------------------------------------------------
template<int NKG>
__device__ __forceinline__ void mma_chunk_h(uint32_t a0, uint32_t a1, uint32_t b0,
                                            float acc[2][8][4]) {
#pragma unroll
    for (int kg = 0; kg < NKG; ++kg) {
        uint32_t a[2][4];
        ldsm4(a[0], a0 + kg * 32);
        ldsm4(a[1], a1 + kg * 32);
#pragma unroll
        for (int p = 0; p < 4; ++p) {
            uint32_t b[4];
            ldsm4(b, b0 + p * (16 * LDWH * 2) + kg * 32);
            mma16(acc[0][2 * p],     a[0], b + 0);
            mma16(acc[0][2 * p + 1], a[0], b + 2);
            mma16(acc[1][2 * p],     a[1], b + 0);
            mma16(acc[1][2 * p + 1], a[1], b + 2);
        }
    }
}

// GELU(acc+bias) -> sA fp16 (natural layout)
__device__ __forceinline__ void epilogue_gelu_h(float acc[2][8][4],
                                                const float* __restrict__ bias,
                                                __half* __restrict__ sAh,
                                                const float4* __restrict__ lut,
                                                int wm, int wn, int g, int t) {
#pragma unroll
    for (int nt = 0; nt < 8; ++nt) {
        const int col = wn * 64 + nt * 8 + 2 * t;
        const float2 bb = *(const float2*)&bias[col];
#pragma unroll
        for (int mt = 0; mt < 2; ++mt) {
            const int row = wm * 32 + mt * 16 + g;
            const __half2 v0 = __floats2half2_rn(gelu_lut(acc[mt][nt][0] + bb.x, lut),
                                                 gelu_lut(acc[mt][nt][1] + bb.y, lut));
            const __half2 v1 = __floats2half2_rn(gelu_lut(acc[mt][nt][2] + bb.x, lut),
                                                 gelu_lut(acc[mt][nt][3] + bb.y, lut));
            *(__half2*)&sAh[row * LDAH + col]       = v0;
            *(__half2*)&sAh[(row + 8) * LDAH + col] = v1;
        }
    }
}

// stage k-chunk q (cols [64q,64q+64) of all 256 n-rows) into smem
__device__ __forceinline__ void stage_chunk(__half* __restrict__ sWh,
                                            const __half* __restrict__ gW,
                                            int q, int tid) {
#pragma unroll
    for (int i = 0; i < 4; ++i) {
        const int e   = tid + i * 512;       // 0..2047
        const int row = e >> 3, seg = (e & 7) * 8;
        cp16h(&sWh[row * LDWH + q * 64 + seg], &gW[row * NH + q * 64 + seg]);
    }
}

// one full layer with chunk-slot recycling for the next layer's weights
__device__ __forceinline__ void run_layer_h(const __half* __restrict__ Wnext,
                                            const float* __restrict__ bias,
                                            __half* __restrict__ sAh,
                                            __half* __restrict__ sWh,
                                            const float4* __restrict__ lut,
                                            uint32_t aA0, uint32_t aA1, uint32_t bA,
                                            int tid, int wm, int wn, int g, int t) {
    float acc[2][8][4];
#pragma unroll
    for (int mt = 0; mt < 2; ++mt)
#pragma unroll
        for (int nt = 0; nt < 8; ++nt)
#pragma unroll
            for (int i = 0; i < 4; ++i) acc[mt][nt][i] = 0.0f;

#pragma unroll 1
    for (int q = 0; q < 4; ++q) {
        mma_chunk_h<4>(aA0 + q * 128, aA1 + q * 128, bA + q * 128, acc);
        __syncthreads();                               // chunk q fully consumed
        if (Wnext) { stage_chunk(sWh, Wnext, q, tid); cp_commit(); }
    }
    epilogue_gelu_h(acc, bias, sAh, lut, wm, wn, g, t);
    if (Wnext) cp_wait0();
    __syncthreads();
}

// ---------------------------------------------------------------------------
// prep: transpose-pack weights to fp16 [n][k]
// ---------------------------------------------------------------------------
__global__ void prep_weights_h(const float* __restrict__ W1,
                               const float* __restrict__ W2,
                               const float* __restrict__ W3,
                               const float* __restrict__ W4) {
    const int i = blockIdx.x * 256 + threadIdx.x;   // 0..32767
    const int n = i >> 7, kp = i & 127;
    const int k0 = 2 * kp;
    ((__half2*)g_W2h)[n * 128 + kp] = __floats2half2_rn(W2[k0 * NH + n], W2[(k0 + 1) * NH + n]);
    ((__half2*)g_W3h)[n * 128 + kp] = __floats2half2_rn(W3[k0 * NH + n], W3[(k0 + 1) * NH + n]);
    ((__half2*)g_W4h)[n * 128 + kp] = __floats2half2_rn(W4[k0 * NH + n], W4[(k0 + 1) * NH + n]);
    if (kp < 16) {
        const float a = (k0     < 25) ? W1[k0 * NH + n]       : 0.0f;
        const float b = (k0 + 1 < 25) ? W1[(k0 + 1) * NH + n] : 0.0f;
        ((__half2*)g_W1h)[n * 16 + kp] = __floats2half2_rn(a, b);
    }
}

// precompute base1 = b1 + emb[traj] @ W1[25:153, :]   (fp32)
__global__ void base1_kernel(const float* __restrict__ emb,
                             const int* __restrict__ traj,
                             const float* __restrict__ W1,
                             const float* __restrict__ b1) {
    const int n  = threadIdx.x;
    const int tr = traj ? traj[0] : 3;
    float s = b1[n];
    const float* e = emb + tr * 128;
#pragma unroll 8
    for (int d = 0; d < 128; ++d)
        s = fmaf(e[d], W1[(25 + d) * NH + n], s);
    g_base1[n] = s;
}

// ---------------------------------------------------------------------------
// main fused kernel
// ---------------------------------------------------------------------------
__global__ void __launch_bounds__(512, 1)
stress_mlp(const float* __restrict__ Fg, const float* __restrict__ Cg,
           const float* __restrict__ b2,
           const float* __restrict__ b3,
           const float* __restrict__ b4,
           const float* __restrict__ W5, const float* __restrict__ b5,
           float* __restrict__ out) {
    extern __shared__ char smem[];
    __half* sAh = (__half*)(smem + OFF_SA);
    __half* sWh = (__half*)(smem + OFF_SW);
    float*  sR  = (float*)(smem + OFF_SR);
    float*  sF  = (float*)(smem + OFF_SF);
    float*  sW5 = (float*)(smem + OFF_SW5);
    float4* sLUT= (float4*)(smem + OFF_LUT);

    const int tid  = threadIdx.x;
    const int m0   = blockIdx.x * MTILE;
    const int warp = tid >> 5, lane = tid & 31;
    const int wm = warp >> 2, wn = warp & 3;
    const int g  = lane >> 2, t  = lane & 3;

    // lane-resolved ldmatrix base addresses
    const uint32_t saB = (uint32_t)__cvta_generic_to_shared(sAh);
    const uint32_t swB = (uint32_t)__cvta_generic_to_shared(sWh);
    const int arow  = wm * 32 + (lane & 15);
    const int akoff = (lane & 16) >> 1;                    // 0 or 8 halfs
    const uint32_t aA0 = saB + (arow * LDAH + akoff) * 2;
    const uint32_t aA1 = saB + ((arow + 16) * LDAH + akoff) * 2;
    const int brow  = wn * 64 + ((lane & 16) >> 1) + (lane & 7);
    const uint32_t bA  = swB + (brow * LDWH + (lane & 8)) * 2;

    // ----- issue all prologue cp.async (W1, W2 chunks 1..3, W5) ------------
#pragma unroll
    for (int i = 0; i < 2; ++i) {
        const int e = tid + i * 512;          // 0..1023
        const int row = e >> 2, seg = (e & 3) * 8;
        cp16h(&sWh[row * LDWH + seg], &g_W1h[row * 32 + seg]);
    }
    stage_chunk(sWh, g_W2h, 1, tid);
    stage_chunk(sWh, g_W2h, 2, tid);
    stage_chunk(sWh, g_W2h, 3, tid);
    cp16f(&sW5[tid * 4], &W5[tid * 4]);
    if (tid < 64) cp16f(&sW5[(512 + tid) * 4], &W5[(512 + tid) * 4]);
    cp_commit();

    // ---------------- prologue: SVD math (0..127) | GELU LUT (128..511) ----
    if (tid < MTILE) {
        const int r  = tid;
        const int gr = m0 + r;
        float f[9], c9[9];
#pragma unroll
        for (int i = 0; i < 9; ++i) { f[i] = Fg[gr * 9 + i]; c9[i] = Cg[gr * 9 + i]; }

        const float g00 = f[0]*f[0] + f[3]*f[3] + f[6]*f[6];
        const float g01 = f[0]*f[1] + f[3]*f[4] + f[6]*f[7];
        const float g02 = f[0]*f[2] + f[3]*f[5] + f[6]*f[8];
        const float g11 = f[1]*f[1] + f[4]*f[4] + f[7]*f[7];
        const float g12 = f[1]*f[2] + f[4]*f[5] + f[7]*f[8];
        const float g22 = f[2]*f[2] + f[5]*f[5] + f[8]*f[8];
        const float det = f[0]*(f[4]*f[8] - f[5]*f[7])
                        - f[1]*(f[3]*f[8] - f[5]*f[6])
                        + f[2]*(f[3]*f[7] - f[4]*f[6]);

        const float q3 = (g00 + g11 + g22) * (1.0f / 3.0f);
        const float d0 = g00 - q3, d1 = g11 - q3, d2 = g22 - q3;
        const float p1 = g01*g01 + g02*g02 + g12*g12;
        const float p2 = d0*d0 + d1*d1 + d2*d2 + 2.0f * p1;
        float l1, l2, l3;
        if (p2 < 1e-30f) { l1 = l2 = l3 = q3; }
        else {
            const float p  = sqrtf(p2 * (1.0f / 6.0f));
            const float ip = 1.0f / p;
            const float b00 = d0*ip, b11 = d1*ip, b22 = d2*ip;
            const float b01 = g01*ip, b02 = g02*ip, b12 = g12*ip;
            const float detB = b00*(b11*b22 - b12*b12)
                             - b01*(b01*b22 - b12*b02)
                             + b02*(b01*b12 - b11*b02);
            const float rr  = fminf(fmaxf(0.5f * detB, -1.0f), 1.0f);
            const float phi = acosf(rr) * (1.0f / 3.0f);
            l1 = q3 + 2.0f * p * cosf(phi);
            l3 = q3 + 2.0f * p * cosf(phi + 2.0943951023931953f);
            l2 = 3.0f * q3 - l1 - l3;
        }
        const float s1 = sqrtf(fmaxf(l1, 0.0f));
        const float s2 = sqrtf(fmaxf(l2, 0.0f));
        const float s3 = sqrtf(fmaxf(l3, 0.0f));

        float R9[9];
#pragma unroll
        for (int i = 0; i < 9; ++i) R9[i] = f[i];
#pragma unroll
        for (int it = 0; it < 5; ++it) {
            const float c00 = R9[4]*R9[8] - R9[5]*R9[7];
            const float c01 = R9[5]*R9[6] - R9[3]*R9[8];
            const float c02 = R9[3]*R9[7] - R9[4]*R9[6];
            const float c10 = R9[2]*R9[7] - R9[1]*R9[8];
            const float c11 = R9[0]*R9[8] - R9[2]*R9[6];
            const float c12 = R9[1]*R9[6] - R9[0]*R9[7];
            const float c20 = R9[1]*R9[5] - R9[2]*R9[4];
            const float c21 = R9[2]*R9[3] - R9[0]*R9[5];
            const float c22 = R9[0]*R9[4] - R9[1]*R9[3];
            const float dd  = R9[0]*c00 + R9[1]*c01 + R9[2]*c02;
            const float h   = 0.5f / dd;
            R9[0] = 0.5f*R9[0] + c00*h;  R9[1] = 0.5f*R9[1] + c01*h;  R9[2] = 0.5f*R9[2] + c02*h;
            R9[3] = 0.5f*R9[3] + c10*h;  R9[4] = 0.5f*R9[4] + c11*h;  R9[5] = 0.5f*R9[5] + c12*h;
            R9[6] = 0.5f*R9[6] + c20*h;  R9[7] = 0.5f*R9[7] + c21*h;  R9[8] = 0.5f*R9[8] + c22*h;
        }

        float fe[25];
        fe[0] = s1 - 1.0f; fe[1] = s2 - 1.0f; fe[2] = s3 - 1.0f;
        fe[3] = g00 - 1.0f; fe[4]  = g01;        fe[5]  = g02;
        fe[6] = g01;        fe[7]  = g11 - 1.0f; fe[8]  = g12;
        fe[9] = g02;        fe[10] = g12;        fe[11] = g22 - 1.0f;
        fe[12] = det - 1.0f;
        fe[13] = logf(det) - 1.0f;
        const float f00 = fmaxf(f[0], 1e-6f);
        fe[14] = f00 - 1.0f;
        fe[15] = logf(f00) - 1.0f;
#pragma unroll
        for (int i = 0; i < 9; ++i) fe[16 + i] = c9[i];
        __half* fr = &sAh[r * LDAH];
#pragma unroll
        for (int k = 0; k < 25; ++k) fr[k] = __float2half_rn(fe[k]);
#pragma unroll
        for (int k = 25; k < 32; ++k) fr[k] = __ushort_as_half((unsigned short)0);
#pragma unroll
        for (int i = 0; i < 9; ++i) { sR[r * 9 + i] = R9[i]; sF[r * 9 + i] = f[i]; }
    } else {
        // GELU quadratic LUT: bin b covers [GLO + b*GDX, GLO + (b+1)*GDX)
        // fit through (x0, xm, x1) with exact erf-GELU; stored (xm, a2, a1, a0)
        for (int b = tid - MTILE; b < GBINS; b += 512 - MTILE) {
            const float x0 = GLO + b * GDX;
            const float xm = x0 + 0.5f * GDX;
            const float x1 = x0 + GDX;
            const float g0 = gelu_exact(x0);
            const float gm = gelu_exact(xm);
            const float g1 = gelu_exact(x1);
            const float hh = 0.5f * GDX;                       // 0.015625
            const float a1c = (g1 - g0) / (2.0f * hh);
            const float a2c = (g0 - 2.0f * gm + g1) / (2.0f * hh * hh);
            sLUT[b] = make_float4(xm, a2c, a1c, gm);
        }
    }
    cp_wait0();
    __syncthreads();

    // ---------------- layer 1 (K=32 -> 2 k16 steps, chunk slot 0) ----------
    {
        float acc[2][8][4];
#pragma unroll
        for (int mt = 0; mt < 2; ++mt)
#pragma unroll
            for (int nt = 0; nt < 8; ++nt)
#pragma unroll
                for (int i = 0; i < 4; ++i) acc[mt][nt][i] = 0.0f;
        mma_chunk_h<2>(aA0, aA1, bA, acc);
        __syncthreads();
        stage_chunk(sWh, g_W2h, 0, tid);   // W2 chunk 0 over W1
        cp_commit();
        epilogue_gelu_h(acc, g_base1, sAh, sLUT, wm, wn, g, t);
        cp_wait0();
        __syncthreads();
    }

    // ---------------- layers 2..4 ------------------------------------------
    run_layer_h(g_W3h,   b2, sAh, sWh, sLUT, aA0, aA1, bA, tid, wm, wn, g, t);
    run_layer_h(g_W4h,   b3, sAh, sWh, sLUT, aA0, aA1, bA, tid, wm, wn, g, t);
    run_layer_h(nullptr, b4, sAh, sWh, sLUT, aA0, aA1, bA, tid, wm, wn, g, t);

    // ---------------- layer 5 + stress epilogue ----------------------------
    {
        const int row = tid >> 2, q4 = tid & 3;
        float a9[9] = {0, 0, 0, 0, 0, 0, 0, 0, 0};
#pragma unroll 4
        for (int i = 0; i < 32; ++i) {
            const int p  = (i << 2) + q4;                  // pair 0..127 -> k = 2p,2p+1
            const __half2 h = *(const __half2*)&sAh[row * LDAH + 2 * p];
            const float a0 = __low2float(h), a1 = __high2float(h);
            const int k0 = 2 * p;
#pragma unroll
            for (int j = 0; j < 9; ++j)
                a9[j] = fmaf(a1, sW5[(k0 + 1) * 9 + j], fmaf(a0, sW5[k0 * 9 + j], a9[j]));
        }
#pragma unroll
        for (int j = 0; j < 9; ++j) {
            a9[j] += __shfl_xor_sync(0xffffffffu, a9[j], 1);
            a9[j] += __shfl_xor_sync(0xffffffffu, a9[j], 2);
        }
        if (q4 == 0) {
            float x[9];
#pragma unroll
            for (int j = 0; j < 9; ++j) x[j] = a9[j] + __ldg(&b5[j]);
            float S[9];
            S[0] = x[0]; S[4] = x[4]; S[8] = x[8];
            S[1] = S[3] = 0.5f * (x[1] + x[3]);
            S[2] = S[6] = 0.5f * (x[2] + x[6]);
            S[5] = S[7] = 0.5f * (x[5] + x[7]);
            float R[9], Fv[9];
#pragma unroll
            for (int i = 0; i < 9; ++i) { R[i] = sR[row * 9 + i]; Fv[i] = sF[row * 9 + i]; }
            float P[9];
#pragma unroll
            for (int i = 0; i < 3; ++i)
#pragma unroll
                for (int j = 0; j < 3; ++j)
                    P[3 * i + j] = R[3 * i] * S[j] + R[3 * i + 1] * S[3 + j] + R[3 * i + 2] * S[6 + j];
            float* o = out + (size_t)(m0 + row) * 9;
#pragma unroll
            for (int i = 0; i < 3; ++i)
#pragma unroll
                for (int j = 0; j < 3; ++j)
                    o[3 * i + j] = P[3 * i] * Fv[3 * j] + P[3 * i + 1] * Fv[3 * j + 1] + P[3 * i + 2] * Fv[3 * j + 2];
        }
    }
}

// ---------------------------------------------------------------------------
// launch
// ---------------------------------------------------------------------------
extern "C" void kernel_launch(void* const* d_in, const int* in_sizes, int n_in,
                              void* d_out, int out_size) {
    const float* F   = (const float*)d_in[0];
    const float* C   = (const float*)d_in[1];
    const float* emb = (const float*)d_in[2];
    const int*   traj = nullptr;
    int base = 3;
    if (n_in >= 14) { traj = (const int*)d_in[3]; base = 4; }
    const float* W1 = (const float*)d_in[base + 0];
    const float* b1 = (const float*)d_in[base + 1];
    const float* W2 = (const float*)d_in[base + 2];
    const float* b2 = (const float*)d_in[base + 3];
    const float* W3 = (const float*)d_in[base + 4];
    const float* b3 = (const float*)d_in[base + 5];
    const float* W4 = (const float*)d_in[base + 6];
    const float* b4 = (const float*)d_in[base + 7];
    const float* W5 = (const float*)d_in[base + 8];
    const float* b5 = (const float*)d_in[base + 9];
    float* out = (float*)d_out;

    const int B = in_sizes[0] / 9;

    prep_weights_h<<<128, 256>>>(W1, W2, W3, W4);
    base1_kernel<<<1, 256>>>(emb, traj, W1, b1);

    cudaFuncSetAttribute(stress_mlp, cudaFuncAttributeMaxDynamicSharedMemorySize, SMEM_BYTES);
    stress_mlp<<<B / MTILE, 512, SMEM_BYTES>>>(F, C, b2, b3, b4, W5, b5, out);
}